// round 7
// baseline (speedup 1.0000x reference)
#include <cuda_runtime.h>
#include <cstdint>
#include <cstdio>

#define VOCAB  50257
#define EMBED  256
#define RESV   2048
#define SQV    225
#define BB     4
#define TT     512
#define NPOS   (BB*TT)                     // 2048
#define OUT_LOGITS ((size_t)NPOS*(size_t)VOCAB)
#define SCAN_CTAS 128
#define RPC    16                          // W_hh rows per CTA
#define RED_STRIDE 65                      // padded float4 stride for reduction buffer
#define SCAN_SMEM ((2048 + RPC*RED_STRIDE) * 16)   // sh(32KB) + red4(~16.6KB)

// ---------------- scratch (static device memory; no allocations) ----------------
__device__ float g_C[(size_t)RESV*EMBED];          // W_ih @ W_in  [2048,256]
__device__ float g_xin[(size_t)NPOS*RESV];         // [p, s] p=b*T+t   (16 MB)
__device__ float g_states[(size_t)NPOS*RESV];      // [p, r]            (16 MB)
__device__ float g_h[2*BB*RESV];                   // double-buffered h
__device__ float g_lg1[(size_t)NPOS*SQV];          // logits1 -> lp1 in place
__device__ float g_lg2[(size_t)NPOS*SQV];
__device__ float g_nll[NPOS];
__device__ int   g_msk[NPOS];
__device__ unsigned g_cnt;                         // single arrival counter

// packed f32x2 FMA: d = a*b + d (element-wise on two fp32 lanes)
__device__ __forceinline__ void ffma2(unsigned long long& d,
                                      unsigned long long a, unsigned long long b) {
    asm("fma.rn.f32x2 %0, %1, %2, %0;" : "+l"(d) : "l"(a), "l"(b));
}
__device__ __forceinline__ float f32x2_sum(unsigned long long v) {
    unsigned lo = (unsigned)(v & 0xffffffffull);
    unsigned hi = (unsigned)(v >> 32);
    return __uint_as_float(lo) + __uint_as_float(hi);
}

// ---------------- init ----------------
__global__ void init_kernel() {
    int tid = threadIdx.x;
    for (int i = tid; i < 2*BB*RESV; i += blockDim.x) g_h[i] = 0.f;
    if (tid == 0) g_cnt = 0u;
}

// ---------------- fp32 GEMM with register prefetch: D[M,N] = A[M,K] @ B[K,N] ----------------
__global__ void __launch_bounds__(256) gemm_nn_kernel(
    const float* __restrict__ A, const float* __restrict__ B,
    float* __restrict__ D, int M, int N, int K)
{
    __shared__ float As[64][17];
    __shared__ float Bs[16][68];
    const int tid = threadIdx.x;
    const int tx = tid & 15, ty = tid >> 4;
    const int m0 = blockIdx.y*64, n0 = blockIdx.x*64;
    float acc[4][4] = {};
    float ra[4], rb[4];

    // prologue: load k0 = 0
#pragma unroll
    for (int i = 0; i < 4; ++i) {
        int e = tid*4 + i; int m = e >> 4, k = e & 15;
        ra[i] = A[(size_t)(m0+m)*K + k];
    }
#pragma unroll
    for (int i = 0; i < 4; ++i) {
        int e = tid*4 + i; int k = e >> 6, n = e & 63;
        int gn = n0 + n;
        rb[i] = (gn < N) ? B[(size_t)k*N + gn] : 0.f;
    }

    for (int k0 = 0; k0 < K; k0 += 16) {
#pragma unroll
        for (int i = 0; i < 4; ++i) {
            int e = tid*4 + i; int m = e >> 4, k = e & 15;
            As[m][k] = ra[i];
        }
#pragma unroll
        for (int i = 0; i < 4; ++i) {
            int e = tid*4 + i; int k = e >> 6, n = e & 63;
            Bs[k][n] = rb[i];
        }
        __syncthreads();

        if (k0 + 16 < K) {
#pragma unroll
            for (int i = 0; i < 4; ++i) {
                int e = tid*4 + i; int m = e >> 4, k = e & 15;
                ra[i] = A[(size_t)(m0+m)*K + k0 + 16 + k];
            }
#pragma unroll
            for (int i = 0; i < 4; ++i) {
                int e = tid*4 + i; int k = e >> 6, n = e & 63;
                int gn = n0 + n;
                rb[i] = (gn < N) ? B[(size_t)(k0+16+k)*N + gn] : 0.f;
            }
        }
#pragma unroll
        for (int kk = 0; kk < 16; ++kk) {
            float a[4], bv[4];
#pragma unroll
            for (int i = 0; i < 4; ++i) a[i] = As[ty*4+i][kk];
#pragma unroll
            for (int j = 0; j < 4; ++j) bv[j] = Bs[kk][tx*4+j];
#pragma unroll
            for (int i = 0; i < 4; ++i)
#pragma unroll
                for (int j = 0; j < 4; ++j) acc[i][j] = fmaf(a[i], bv[j], acc[i][j]);
        }
        __syncthreads();
    }
#pragma unroll
    for (int i = 0; i < 4; ++i) {
        int m = m0 + ty*4 + i;
#pragma unroll
        for (int j = 0; j < 4; ++j) {
            int n = n0 + tx*4 + j;
            if (m < M && n < N) D[(size_t)m*N + n] = acc[i][j];
        }
    }
}

// ---- D[M,N] = gatherA[M,K] @ Bm[N,K]^T (+bias), register prefetch. ----
__global__ void __launch_bounds__(256) gemm_nt_kernel(
    const float* __restrict__ A, const float* __restrict__ Bm,
    const float* __restrict__ bias, const int* __restrict__ gidx,
    float* __restrict__ D, int M, int N, int K, int useGather, int useBias)
{
    __shared__ float As[64][17];
    __shared__ float Bs[64][17];
    const int tid = threadIdx.x;
    const int tx = tid & 15, ty = tid >> 4;
    const int m0 = blockIdx.y*64, n0 = blockIdx.x*64;
    float acc[4][4] = {};
    float ra[4], rb[4];
    int arow[4], brow[4];

#pragma unroll
    for (int i = 0; i < 4; ++i) {
        int e = tid*4 + i; int m = e >> 4;
        int gm = m0 + m;
        arow[i] = useGather ? gidx[gm] : gm;
        int n = e >> 4;
        int gn = n0 + n;
        brow[i] = (gn < N) ? gn : -1;
    }
    // prologue: k0 = 0
#pragma unroll
    for (int i = 0; i < 4; ++i) {
        int e = tid*4 + i; int k = e & 15;
        ra[i] = A[(size_t)arow[i]*K + k];
        rb[i] = (brow[i] >= 0) ? Bm[(size_t)brow[i]*K + k] : 0.f;
    }

    for (int k0 = 0; k0 < K; k0 += 16) {
#pragma unroll
        for (int i = 0; i < 4; ++i) {
            int e = tid*4 + i; int m = e >> 4, k = e & 15;
            As[m][k] = ra[i];
            Bs[m][k] = rb[i];   // n == m bitfield (e>>4)
        }
        __syncthreads();

        if (k0 + 16 < K) {
#pragma unroll
            for (int i = 0; i < 4; ++i) {
                int e = tid*4 + i; int k = e & 15;
                ra[i] = A[(size_t)arow[i]*K + k0 + 16 + k];
                rb[i] = (brow[i] >= 0) ? Bm[(size_t)brow[i]*K + k0 + 16 + k] : 0.f;
            }
        }
#pragma unroll
        for (int kk = 0; kk < 16; ++kk) {
            float a[4], bv[4];
#pragma unroll
            for (int i = 0; i < 4; ++i) a[i] = As[ty*4+i][kk];
#pragma unroll
            for (int j = 0; j < 4; ++j) bv[j] = Bs[tx*4+j][kk];
#pragma unroll
            for (int i = 0; i < 4; ++i)
#pragma unroll
                for (int j = 0; j < 4; ++j) acc[i][j] = fmaf(a[i], bv[j], acc[i][j]);
        }
        __syncthreads();
    }
#pragma unroll
    for (int i = 0; i < 4; ++i) {
        int m = m0 + ty*4 + i;
#pragma unroll
        for (int j = 0; j < 4; ++j) {
            int n = n0 + tx*4 + j;
            if (m < M && n < N)
                D[(size_t)m*N + n] = acc[i][j] + (useBias ? bias[n] : 0.f);
        }
    }
}

// ---------------- persistent recurrent scan (512 threads) ----------------
// 128 CTAs x 512 threads. CTA owns rows [cta*16, cta*16+16).
// Thread (ks = tid>>3 in 0..63, rg = tid&7): rows rg, rg+8; k-cols {4ks+256q..+3}.
// W register-resident (2 rows x 32 cols = 64 floats). 16 warps hide latency.
__global__ void __launch_bounds__(512, 1) scan_kernel(
    const float* __restrict__ W_hh, const float* __restrict__ b_hh)
{
    extern __shared__ float4 smem4[];
    float4* sh4  = smem4;                 // [BB][512] float4 (h staging, 32KB)
    float4* red4 = smem4 + 2048;          // [16][RED_STRIDE] float4 partials

    const int cta = blockIdx.x, tid = threadIdx.x;
    const int row0 = cta*RPC;
    const int ks = tid >> 3, rg = tid & 7;

    // W_hh slice -> registers (packed pairs): rows rg, rg+8
    ulonglong2 w2[2][8];
#pragma unroll
    for (int j = 0; j < 2; ++j)
#pragma unroll
        for (int q = 0; q < 8; ++q)
            w2[j][q] = *reinterpret_cast<const ulonglong2*>(
                &W_hh[(size_t)(row0 + rg + 8*j)*RESV + 4*ks + 256*q]);

    // finalizer constants: threads with (tid&7)==0 own output o = tid>>3
    const int o     = tid >> 3;           // 0..63
    const int rloc  = o >> 2;             // local row 0..15
    const int bidx  = o & 3;              // batch
    const bool wr   = (tid & 7) == 0;
    const float bias_v = wr ? b_hh[row0 + rloc] : 0.f;

    const ulonglong2* sh2 = reinterpret_cast<const ulonglong2*>(sh4);
    unsigned* cntp = &g_cnt;

    for (int t = 0; t < TT; ++t) {
        // preload xin for this step's output
        float xin_v = 0.f;
        if (wr) xin_v = __ldcg(&g_xin[(size_t)(bidx*TT + t)*RESV + row0 + rloc]);

        // stage h_t into smem (contiguous 32KB, double-buffered)
        const float4* hsrc = reinterpret_cast<const float4*>(&g_h[(t&1)*BB*RESV]);
        for (int i = tid; i < BB*RESV/4; i += 512)
            sh4[i] = __ldcg(hsrc + i);
        __syncthreads();                  // s1: stage complete (orders red4 reuse too)

        unsigned long long acc2[2][4];    // [j][b] packed (even-k, odd-k)
#pragma unroll
        for (int j = 0; j < 2; ++j)
#pragma unroll
            for (int b = 0; b < 4; ++b) acc2[j][b] = 0ull;

#pragma unroll
        for (int q = 0; q < 8; ++q) {
            const int hoff = ks + 64*q;
            const ulonglong2 h0 = sh2[0*512 + hoff];
            const ulonglong2 h1 = sh2[1*512 + hoff];
            const ulonglong2 h2 = sh2[2*512 + hoff];
            const ulonglong2 h3 = sh2[3*512 + hoff];
#pragma unroll
            for (int j = 0; j < 2; ++j) {
                const ulonglong2 wv = w2[j][q];
                ffma2(acc2[j][0], wv.x, h0.x); ffma2(acc2[j][0], wv.y, h0.y);
                ffma2(acc2[j][1], wv.x, h1.x); ffma2(acc2[j][1], wv.y, h1.y);
                ffma2(acc2[j][2], wv.x, h2.x); ffma2(acc2[j][2], wv.y, h2.y);
                ffma2(acc2[j][3], wv.x, h3.x); ffma2(acc2[j][3], wv.y, h3.y);
            }
        }

        // partials: red4[row][ks] (rows rg, rg+8)
#pragma unroll
        for (int j = 0; j < 2; ++j)
            red4[(rg + 8*j)*RED_STRIDE + ks] =
                make_float4(f32x2_sum(acc2[j][0]), f32x2_sum(acc2[j][1]),
                            f32x2_sum(acc2[j][2]), f32x2_sum(acc2[j][3]));
        __syncthreads();                  // s2: partials visible

        // reduce: thread (o = tid>>3, sp = tid&7) sums ks = sp + 8*i
        {
            const int sp = tid & 7;
            const float* redf = reinterpret_cast<const float*>(red4);
            float s = 0.f;
#pragma unroll
            for (int i = 0; i < 8; ++i)
                s += redf[(rloc*RED_STRIDE + sp + 8*i)*4 + bidx];
            s += __shfl_xor_sync(0xffffffffu, s, 1);
            s += __shfl_xor_sync(0xffffffffu, s, 2);
            s += __shfl_xor_sync(0xffffffffu, s, 4);

            if (wr) {
                float hv = tanhf(s + xin_v + bias_v);
                __stcg(&g_h[((t+1)&1)*BB*RESV + bidx*RESV + row0 + rloc], hv);
                __stcg(&g_states[(size_t)(bidx*TT + t)*RESV + row0 + rloc], hv);
            }
        }
        __syncthreads();                  // s3: all writers' stores issued

        // arrival + departure: tid0 only (release-add, acquire-spin)
        if (tid == 0) {
            asm volatile("red.release.gpu.global.add.u32 [%0], %1;"
                         :: "l"(cntp), "r"(1u) : "memory");
            const unsigned target = (unsigned)(SCAN_CTAS*(t+1));
            unsigned v;
            do {
                asm volatile("ld.global.acquire.gpu.u32 %0, [%1];"
                             : "=r"(v) : "l"(cntp) : "memory");
            } while (v < target);
        }
        __syncthreads();                  // releases CTA; HB: release->acquire->bar
    }
}

// ---------------- log-softmax in place: rows of length 225 ----------------
__global__ void __launch_bounds__(128) logsoftmax_kernel(float* __restrict__ X)
{
    int warp = (blockIdx.x*blockDim.x + threadIdx.x) >> 5;
    int lane = threadIdx.x & 31;
    if (warp >= NPOS) return;
    float* row = X + (size_t)warp*SQV;
    float v[8]; float m = -1e30f;
#pragma unroll
    for (int i = 0; i < 8; ++i) {
        int c = lane + 32*i;
        v[i] = (c < SQV) ? row[c] : -1e30f;
        m = fmaxf(m, v[i]);
    }
#pragma unroll
    for (int o = 16; o; o >>= 1) m = fmaxf(m, __shfl_xor_sync(0xffffffffu, m, o));
    float s = 0.f;
#pragma unroll
    for (int i = 0; i < 8; ++i) {
        int c = lane + 32*i;
        if (c < SQV) s += expf(v[i] - m);
    }
#pragma unroll
    for (int o = 16; o; o >>= 1) s += __shfl_xor_sync(0xffffffffu, s, o);
    float ls = m + logf(s);
#pragma unroll
    for (int i = 0; i < 8; ++i) {
        int c = lane + 32*i;
        if (c < SQV) row[c] = v[i] - ls;
    }
}

// ---------------- per-position NLL ----------------
__global__ void nll_kernel(const int* __restrict__ targets)
{
    int p = blockIdx.x*blockDim.x + threadIdx.x;
    if (p >= NPOS) return;
    int tgt = targets[p];
    int mask = (tgt != -1);
    int st = mask ? tgt : 0;
    int tr = st / SQV, tc = st % SQV;
    float v = 0.f;
    if (mask) v = -(g_lg1[(size_t)p*SQV + tr] + g_lg2[(size_t)p*SQV + tc]);
    g_nll[p] = v;
    g_msk[p] = mask;
}

// ---------------- deterministic loss reduction + h_n copy ----------------
__global__ void __launch_bounds__(1024) finalize_kernel(float* __restrict__ out)
{
    __shared__ float ss[1024];
    __shared__ int   sc[1024];
    int tid = threadIdx.x;
    ss[tid] = g_nll[tid] + g_nll[tid + 1024];
    sc[tid] = g_msk[tid] + g_msk[tid + 1024];
    __syncthreads();
    for (int o = 512; o; o >>= 1) {
        if (tid < o) { ss[tid] += ss[tid+o]; sc[tid] += sc[tid+o]; }
        __syncthreads();
    }
    if (tid == 0) {
        int c = sc[0] < 1 ? 1 : sc[0];
        out[OUT_LOGITS] = ss[0] / (float)c;
    }
    // h_n = h after step T (T even -> buffer 0)
    for (int i = tid; i < BB*RESV; i += 1024)
        out[OUT_LOGITS + 1 + i] = g_h[i];
}

// ---------------- logits expansion (no div/mod): out[p, r*225+c] = lp1[p,r] + lp2[p,c] ----------------
__global__ void __launch_bounds__(256) expand_kernel(
    const float* __restrict__ lp1, const float* __restrict__ lp2, float* __restrict__ out)
{
    __shared__ float s1[SQV], s2[SQV];
    const int p = blockIdx.x;
    const int tid = threadIdx.x;
    if (tid < SQV) {
        s1[tid] = lp1[(size_t)p*SQV + tid];
        s2[tid] = lp2[(size_t)p*SQV + tid];
    }
    __syncthreads();
    float* o = out + (size_t)p*VOCAB;
    const int w = tid >> 5, lane = tid & 31;
    // VOCAB = 223*225 + 82 : rows 0..222 full (225 cols), row 223 has 82 cols
    for (int r = w; r < 224; r += 8) {
        const float base = s1[r];
        const int lim = (r == 223) ? 82 : SQV;
        float* orow = o + r*SQV;
        for (int c = lane; c < lim; c += 32)
            orow[c] = base + s2[c];
    }
}

// ---------------- launch ----------------
extern "C" void kernel_launch(void* const* d_in, const int* in_sizes, int n_in,
                              void* d_out, int out_size)
{
    const int*   idx     = (const int*)  d_in[0];
    const int*   targets = (const int*)  d_in[1];
    const float* wte     = (const float*)d_in[2];
    const float* W_in    = (const float*)d_in[3];
    const float* W_ih    = (const float*)d_in[4];
    const float* b_ih    = (const float*)d_in[5];
    const float* W_hh    = (const float*)d_in[6];
    const float* b_hh    = (const float*)d_in[7];
    const float* Wh1     = (const float*)d_in[8];
    const float* Wh2     = (const float*)d_in[9];
    float* out = (float*)d_out;

    cudaFuncSetAttribute(scan_kernel, cudaFuncAttributeMaxDynamicSharedMemorySize, SCAN_SMEM);

    float *pC, *pxin, *pstates, *plg1, *plg2;
    cudaGetSymbolAddress((void**)&pC,      g_C);
    cudaGetSymbolAddress((void**)&pxin,    g_xin);
    cudaGetSymbolAddress((void**)&pstates, g_states);
    cudaGetSymbolAddress((void**)&plg1,    g_lg1);
    cudaGetSymbolAddress((void**)&plg2,    g_lg2);

    init_kernel<<<1, 256>>>();

    // C = W_ih @ W_in : [2048, 256]
    gemm_nn_kernel<<<dim3(EMBED/64, RESV/64), 256>>>(W_ih, W_in, pC, RESV, EMBED, RESV);

    // xin[p, s] = wte[idx[p]] . C[s] + b_ih[s] : [2048, 2048]
    gemm_nt_kernel<<<dim3(RESV/64, NPOS/64), 256>>>(
        wte, pC, b_ih, idx, pxin, NPOS, RESV, EMBED, 1, 1);

    // recurrent scan -> g_states (+ g_h double buffer)
    scan_kernel<<<SCAN_CTAS, 512, SCAN_SMEM>>>(W_hh, b_hh);

    // head GEMMs: logits[p, v] = states[p] . Wh[v]
    gemm_nt_kernel<<<dim3((SQV+63)/64, NPOS/64), 256>>>(
        pstates, Wh1, nullptr, nullptr, plg1, NPOS, SQV, RESV, 0, 0);
    gemm_nt_kernel<<<dim3((SQV+63)/64, NPOS/64), 256>>>(
        pstates, Wh2, nullptr, nullptr, plg2, NPOS, SQV, RESV, 0, 0);

    // log-softmax in place (warp per row)
    logsoftmax_kernel<<<(NPOS*32 + 127)/128, 128>>>(plg1);
    logsoftmax_kernel<<<(NPOS*32 + 127)/128, 128>>>(plg2);

    // loss pieces
    nll_kernel<<<(NPOS + 255)/256, 256>>>(targets);
    finalize_kernel<<<1, 1024>>>(out);

    // full-vocab logits expansion
    expand_kernel<<<NPOS, 256>>>(plg1, plg2, out);
}

// round 8
// speedup vs baseline: 1.2275x; 1.2275x over previous
#include <cuda_runtime.h>
#include <cstdint>
#include <cstdio>

#define VOCAB  50257
#define EMBED  256
#define RESV   2048
#define SQV    225
#define BB     4
#define TT     512
#define NPOS   (BB*TT)                     // 2048
#define OUT_LOGITS ((size_t)NPOS*(size_t)VOCAB)
#define SCAN_CTAS 128
#define RPC    16                          // W_hh rows per CTA
#define RED_STRIDE 65                      // padded float4 stride for reduction buffer
#define SCAN_SMEM ((2048 + RPC*RED_STRIDE) * 16)   // sh(32KB) + red4(~16.6KB)

// ---------------- scratch (static device memory; no allocations) ----------------
__device__ float g_C[(size_t)RESV*EMBED];          // W_ih @ W_in  [2048,256]
__device__ float g_xin[(size_t)NPOS*RESV];         // [p, s] p=b*T+t   (16 MB)
__device__ float g_states[(size_t)NPOS*RESV];      // [p, r]            (16 MB)
__device__ float g_h[2*BB*RESV];                   // double-buffered h
__device__ float g_lg1[(size_t)NPOS*SQV];          // logits1 -> lp1 in place
__device__ float g_lg2[(size_t)NPOS*SQV];
__device__ float g_nll[NPOS];
__device__ int   g_msk[NPOS];
__device__ unsigned g_cnt;                         // single arrival counter

// packed f32x2 FMA: d = a*b + d (element-wise on two fp32 lanes)
__device__ __forceinline__ void ffma2(unsigned long long& d,
                                      unsigned long long a, unsigned long long b) {
    asm("fma.rn.f32x2 %0, %1, %2, %0;" : "+l"(d) : "l"(a), "l"(b));
}
__device__ __forceinline__ float f32x2_sum(unsigned long long v) {
    unsigned lo = (unsigned)(v & 0xffffffffull);
    unsigned hi = (unsigned)(v >> 32);
    return __uint_as_float(lo) + __uint_as_float(hi);
}

// ---------------- init ----------------
__global__ void init_kernel() {
    int tid = threadIdx.x;
    for (int i = tid; i < 2*BB*RESV; i += blockDim.x) g_h[i] = 0.f;
    if (tid == 0) g_cnt = 0u;
}

// ---------------- fp32 GEMM with register prefetch: D[M,N] = A[M,K] @ B[K,N] ----------------
__global__ void __launch_bounds__(256) gemm_nn_kernel(
    const float* __restrict__ A, const float* __restrict__ B,
    float* __restrict__ D, int M, int N, int K)
{
    __shared__ float As[64][17];
    __shared__ float Bs[16][68];
    const int tid = threadIdx.x;
    const int tx = tid & 15, ty = tid >> 4;
    const int m0 = blockIdx.y*64, n0 = blockIdx.x*64;
    float acc[4][4] = {};
    float ra[4], rb[4];

#pragma unroll
    for (int i = 0; i < 4; ++i) {
        int e = tid*4 + i; int m = e >> 4, k = e & 15;
        ra[i] = A[(size_t)(m0+m)*K + k];
    }
#pragma unroll
    for (int i = 0; i < 4; ++i) {
        int e = tid*4 + i; int k = e >> 6, n = e & 63;
        int gn = n0 + n;
        rb[i] = (gn < N) ? B[(size_t)k*N + gn] : 0.f;
    }

    for (int k0 = 0; k0 < K; k0 += 16) {
#pragma unroll
        for (int i = 0; i < 4; ++i) {
            int e = tid*4 + i; int m = e >> 4, k = e & 15;
            As[m][k] = ra[i];
        }
#pragma unroll
        for (int i = 0; i < 4; ++i) {
            int e = tid*4 + i; int k = e >> 6, n = e & 63;
            Bs[k][n] = rb[i];
        }
        __syncthreads();

        if (k0 + 16 < K) {
#pragma unroll
            for (int i = 0; i < 4; ++i) {
                int e = tid*4 + i; int m = e >> 4, k = e & 15;
                ra[i] = A[(size_t)(m0+m)*K + k0 + 16 + k];
            }
#pragma unroll
            for (int i = 0; i < 4; ++i) {
                int e = tid*4 + i; int k = e >> 6, n = e & 63;
                int gn = n0 + n;
                rb[i] = (gn < N) ? B[(size_t)(k0+16+k)*N + gn] : 0.f;
            }
        }
#pragma unroll
        for (int kk = 0; kk < 16; ++kk) {
            float a[4], bv[4];
#pragma unroll
            for (int i = 0; i < 4; ++i) a[i] = As[ty*4+i][kk];
#pragma unroll
            for (int j = 0; j < 4; ++j) bv[j] = Bs[kk][tx*4+j];
#pragma unroll
            for (int i = 0; i < 4; ++i)
#pragma unroll
                for (int j = 0; j < 4; ++j) acc[i][j] = fmaf(a[i], bv[j], acc[i][j]);
        }
        __syncthreads();
    }
#pragma unroll
    for (int i = 0; i < 4; ++i) {
        int m = m0 + ty*4 + i;
#pragma unroll
        for (int j = 0; j < 4; ++j) {
            int n = n0 + tx*4 + j;
            if (m < M && n < N) D[(size_t)m*N + n] = acc[i][j];
        }
    }
}

// ---- D[M,N] = gatherA[M,K] @ Bm[N,K]^T (+bias), register prefetch. ----
__global__ void __launch_bounds__(256) gemm_nt_kernel(
    const float* __restrict__ A, const float* __restrict__ Bm,
    const float* __restrict__ bias, const int* __restrict__ gidx,
    float* __restrict__ D, int M, int N, int K, int useGather, int useBias)
{
    __shared__ float As[64][17];
    __shared__ float Bs[64][17];
    const int tid = threadIdx.x;
    const int tx = tid & 15, ty = tid >> 4;
    const int m0 = blockIdx.y*64, n0 = blockIdx.x*64;
    float acc[4][4] = {};
    float ra[4], rb[4];
    int arow[4], brow[4];

#pragma unroll
    for (int i = 0; i < 4; ++i) {
        int e = tid*4 + i; int m = e >> 4;
        int gm = m0 + m;
        arow[i] = useGather ? gidx[gm] : gm;
        int gn = n0 + m;
        brow[i] = (gn < N) ? gn : -1;
    }
#pragma unroll
    for (int i = 0; i < 4; ++i) {
        int e = tid*4 + i; int k = e & 15;
        ra[i] = A[(size_t)arow[i]*K + k];
        rb[i] = (brow[i] >= 0) ? Bm[(size_t)brow[i]*K + k] : 0.f;
    }

    for (int k0 = 0; k0 < K; k0 += 16) {
#pragma unroll
        for (int i = 0; i < 4; ++i) {
            int e = tid*4 + i; int m = e >> 4, k = e & 15;
            As[m][k] = ra[i];
            Bs[m][k] = rb[i];
        }
        __syncthreads();

        if (k0 + 16 < K) {
#pragma unroll
            for (int i = 0; i < 4; ++i) {
                int e = tid*4 + i; int k = e & 15;
                ra[i] = A[(size_t)arow[i]*K + k0 + 16 + k];
                rb[i] = (brow[i] >= 0) ? Bm[(size_t)brow[i]*K + k0 + 16 + k] : 0.f;
            }
        }
#pragma unroll
        for (int kk = 0; kk < 16; ++kk) {
            float a[4], bv[4];
#pragma unroll
            for (int i = 0; i < 4; ++i) a[i] = As[ty*4+i][kk];
#pragma unroll
            for (int j = 0; j < 4; ++j) bv[j] = Bs[tx*4+j][kk];
#pragma unroll
            for (int i = 0; i < 4; ++i)
#pragma unroll
                for (int j = 0; j < 4; ++j) acc[i][j] = fmaf(a[i], bv[j], acc[i][j]);
        }
        __syncthreads();
    }
#pragma unroll
    for (int i = 0; i < 4; ++i) {
        int m = m0 + ty*4 + i;
#pragma unroll
        for (int j = 0; j < 4; ++j) {
            int n = n0 + tx*4 + j;
            if (m < M && n < N)
                D[(size_t)m*N + n] = acc[i][j] + (useBias ? bias[n] : 0.f);
        }
    }
}

// ---- fused dual head GEMM: z = blockIdx.z selects (Wh1->lg1, Wh2->lg2) ----
__global__ void __launch_bounds__(256) gemm_heads_kernel(
    const float* __restrict__ A,
    const float* __restrict__ W1, const float* __restrict__ W2,
    float* __restrict__ D1, float* __restrict__ D2)
{
    const float* Bm = blockIdx.z ? W2 : W1;
    float*       D  = blockIdx.z ? D2 : D1;
    const int M = NPOS, N = SQV, K = RESV;

    __shared__ float As[64][17];
    __shared__ float Bs[64][17];
    const int tid = threadIdx.x;
    const int tx = tid & 15, ty = tid >> 4;
    const int m0 = blockIdx.y*64, n0 = blockIdx.x*64;
    float acc[4][4] = {};
    float ra[4], rb[4];
    int brow[4];

#pragma unroll
    for (int i = 0; i < 4; ++i) {
        int e = tid*4 + i; int m = e >> 4;
        int gn = n0 + m;
        brow[i] = (gn < N) ? gn : -1;
    }
#pragma unroll
    for (int i = 0; i < 4; ++i) {
        int e = tid*4 + i; int m = e >> 4, k = e & 15;
        ra[i] = A[(size_t)(m0+m)*K + k];
        rb[i] = (brow[i] >= 0) ? Bm[(size_t)brow[i]*K + k] : 0.f;
    }

    for (int k0 = 0; k0 < K; k0 += 16) {
#pragma unroll
        for (int i = 0; i < 4; ++i) {
            int e = tid*4 + i; int m = e >> 4, k = e & 15;
            As[m][k] = ra[i];
            Bs[m][k] = rb[i];
        }
        __syncthreads();

        if (k0 + 16 < K) {
#pragma unroll
            for (int i = 0; i < 4; ++i) {
                int e = tid*4 + i; int m = e >> 4, k = e & 15;
                ra[i] = A[(size_t)(m0+m)*K + k0 + 16 + k];
                rb[i] = (brow[i] >= 0) ? Bm[(size_t)brow[i]*K + k0 + 16 + k] : 0.f;
            }
        }
#pragma unroll
        for (int kk = 0; kk < 16; ++kk) {
            float a[4], bv[4];
#pragma unroll
            for (int i = 0; i < 4; ++i) a[i] = As[ty*4+i][kk];
#pragma unroll
            for (int j = 0; j < 4; ++j) bv[j] = Bs[tx*4+j][kk];
#pragma unroll
            for (int i = 0; i < 4; ++i)
#pragma unroll
                for (int j = 0; j < 4; ++j) acc[i][j] = fmaf(a[i], bv[j], acc[i][j]);
        }
        __syncthreads();
    }
#pragma unroll
    for (int i = 0; i < 4; ++i) {
        int m = m0 + ty*4 + i;
#pragma unroll
        for (int j = 0; j < 4; ++j) {
            int n = n0 + tx*4 + j;
            if (m < M && n < N) D[(size_t)m*N + n] = acc[i][j];
        }
    }
}

// ---------------- persistent recurrent scan (round-6 config: 256 thr, 16 chains) ----------------
__global__ void __launch_bounds__(256, 1) scan_kernel(
    const float* __restrict__ W_hh, const float* __restrict__ b_hh)
{
    extern __shared__ float4 smem4[];
    float4* sh4  = smem4;                 // [BB][512] float4 (h staging, 32KB)
    float4* red4 = smem4 + 2048;          // [16][RED_STRIDE] float4 partials

    const int cta = blockIdx.x, tid = threadIdx.x;
    const int row0 = cta*RPC;
    const int ks = tid >> 2, rg = tid & 3;

    // W_hh slice -> registers (packed pairs)
    ulonglong2 w2[4][8];
#pragma unroll
    for (int j = 0; j < 4; ++j)
#pragma unroll
        for (int q = 0; q < 8; ++q)
            w2[j][q] = *reinterpret_cast<const ulonglong2*>(
                &W_hh[(size_t)(row0 + rg + 4*j)*RESV + 4*ks + 256*q]);

    // finalizer constants: threads with (tid&3)==0 own output o = tid>>2
    const int o     = tid >> 2;           // 0..63
    const int rloc  = o >> 2;             // local row 0..15
    const int bidx  = o & 3;              // batch
    const bool wr   = (tid & 3) == 0;
    const float bias_v = wr ? b_hh[row0 + rloc] : 0.f;

    const ulonglong2* sh2 = reinterpret_cast<const ulonglong2*>(sh4);
    unsigned* cntp = &g_cnt;

    for (int t = 0; t < TT; ++t) {
        float xin_v = 0.f;
        if (wr) xin_v = __ldcg(&g_xin[(size_t)(bidx*TT + t)*RESV + row0 + rloc]);

        const float4* hsrc = reinterpret_cast<const float4*>(&g_h[(t&1)*BB*RESV]);
        for (int i = tid; i < BB*RESV/4; i += 256)
            sh4[i] = __ldcg(hsrc + i);
        __syncthreads();                  // s1: stage complete (orders red4 reuse)

        unsigned long long acc2[4][4];
#pragma unroll
        for (int j = 0; j < 4; ++j)
#pragma unroll
            for (int b = 0; b < 4; ++b) acc2[j][b] = 0ull;

#pragma unroll
        for (int q = 0; q < 8; ++q) {
            const int hoff = ks + 64*q;
            const ulonglong2 h0 = sh2[0*512 + hoff];
            const ulonglong2 h1 = sh2[1*512 + hoff];
            const ulonglong2 h2 = sh2[2*512 + hoff];
            const ulonglong2 h3 = sh2[3*512 + hoff];
#pragma unroll
            for (int j = 0; j < 4; ++j) {
                const ulonglong2 wv = w2[j][q];
                ffma2(acc2[j][0], wv.x, h0.x); ffma2(acc2[j][0], wv.y, h0.y);
                ffma2(acc2[j][1], wv.x, h1.x); ffma2(acc2[j][1], wv.y, h1.y);
                ffma2(acc2[j][2], wv.x, h2.x); ffma2(acc2[j][2], wv.y, h2.y);
                ffma2(acc2[j][3], wv.x, h3.x); ffma2(acc2[j][3], wv.y, h3.y);
            }
        }

#pragma unroll
        for (int j = 0; j < 4; ++j)
            red4[(rg + 4*j)*RED_STRIDE + ks] =
                make_float4(f32x2_sum(acc2[j][0]), f32x2_sum(acc2[j][1]),
                            f32x2_sum(acc2[j][2]), f32x2_sum(acc2[j][3]));
        __syncthreads();                  // s2: partials visible

        {
            const int sp = tid & 3;
            const float* redf = reinterpret_cast<const float*>(red4);
            float s = 0.f;
#pragma unroll
            for (int i = 0; i < 16; ++i)
                s += redf[(rloc*RED_STRIDE + sp + 4*i)*4 + bidx];
            s += __shfl_xor_sync(0xffffffffu, s, 1);
            s += __shfl_xor_sync(0xffffffffu, s, 2);

            if (wr) {
                float hv = tanhf(s + xin_v + bias_v);
                __stcg(&g_h[((t+1)&1)*BB*RESV + bidx*RESV + row0 + rloc], hv);
                __stcg(&g_states[(size_t)(bidx*TT + t)*RESV + row0 + rloc], hv);
            }
        }
        __syncthreads();                  // s3: all writers' stores issued

        if (tid == 0) {
            asm volatile("red.release.gpu.global.add.u32 [%0], %1;"
                         :: "l"(cntp), "r"(1u) : "memory");
            const unsigned target = (unsigned)(SCAN_CTAS*(t+1));
            unsigned v;
            do {
                asm volatile("ld.global.acquire.gpu.u32 %0, [%1];"
                             : "=r"(v) : "l"(cntp) : "memory");
            } while (v < target);
        }
        __syncthreads();                  // releases CTA; HB: release->acquire->bar
    }
}

// ---------------- log-softmax in place: rows of length 225 ----------------
__global__ void __launch_bounds__(128) logsoftmax_kernel(float* __restrict__ X)
{
    int warp = (blockIdx.x*blockDim.x + threadIdx.x) >> 5;
    int lane = threadIdx.x & 31;
    if (warp >= NPOS) return;
    float* row = X + (size_t)warp*SQV;
    float v[8]; float m = -1e30f;
#pragma unroll
    for (int i = 0; i < 8; ++i) {
        int c = lane + 32*i;
        v[i] = (c < SQV) ? row[c] : -1e30f;
        m = fmaxf(m, v[i]);
    }
#pragma unroll
    for (int o = 16; o; o >>= 1) m = fmaxf(m, __shfl_xor_sync(0xffffffffu, m, o));
    float s = 0.f;
#pragma unroll
    for (int i = 0; i < 8; ++i) {
        int c = lane + 32*i;
        if (c < SQV) s += expf(v[i] - m);
    }
#pragma unroll
    for (int o = 16; o; o >>= 1) s += __shfl_xor_sync(0xffffffffu, s, o);
    float ls = m + logf(s);
#pragma unroll
    for (int i = 0; i < 8; ++i) {
        int c = lane + 32*i;
        if (c < SQV) row[c] = v[i] - ls;
    }
}

// ---------------- per-position NLL ----------------
__global__ void nll_kernel(const int* __restrict__ targets)
{
    int p = blockIdx.x*blockDim.x + threadIdx.x;
    if (p >= NPOS) return;
    int tgt = targets[p];
    int mask = (tgt != -1);
    int st = mask ? tgt : 0;
    int tr = st / SQV, tc = st % SQV;
    float v = 0.f;
    if (mask) v = -(g_lg1[(size_t)p*SQV + tr] + g_lg2[(size_t)p*SQV + tc]);
    g_nll[p] = v;
    g_msk[p] = mask;
}

// ---------------- deterministic loss reduction + h_n copy ----------------
__global__ void __launch_bounds__(1024) finalize_kernel(float* __restrict__ out)
{
    __shared__ float ss[1024];
    __shared__ int   sc[1024];
    int tid = threadIdx.x;
    ss[tid] = g_nll[tid] + g_nll[tid + 1024];
    sc[tid] = g_msk[tid] + g_msk[tid + 1024];
    __syncthreads();
    for (int o = 512; o; o >>= 1) {
        if (tid < o) { ss[tid] += ss[tid+o]; sc[tid] += sc[tid+o]; }
        __syncthreads();
    }
    if (tid == 0) {
        int c = sc[0] < 1 ? 1 : sc[0];
        out[OUT_LOGITS] = ss[0] / (float)c;
    }
    // h_n = h after step T (T even -> buffer 0)
    for (int i = tid; i < BB*RESV; i += 1024)
        out[OUT_LOGITS + 1 + i] = g_h[i];
}

// ---------------- logits expansion: out[p, r*225+c] = lp1[p,r] + lp2[p,c] ----------------
__global__ void __launch_bounds__(256) expand_kernel(
    const float* __restrict__ lp1, const float* __restrict__ lp2, float* __restrict__ out)
{
    __shared__ float s1[SQV], s2[SQV];
    const int p = blockIdx.x;
    const int tid = threadIdx.x;
    if (tid < SQV) {
        s1[tid] = lp1[(size_t)p*SQV + tid];
        s2[tid] = lp2[(size_t)p*SQV + tid];
    }
    __syncthreads();
    float* o = out + (size_t)p*VOCAB;
    const int w = tid >> 5, lane = tid & 31;
    for (int r = w; r < 224; r += 8) {
        const float base = s1[r];
        const int lim = (r == 223) ? 82 : SQV;
        float* orow = o + r*SQV;
        for (int c = lane; c < lim; c += 32)
            orow[c] = base + s2[c];
    }
}

// ---------------- launch ----------------
extern "C" void kernel_launch(void* const* d_in, const int* in_sizes, int n_in,
                              void* d_out, int out_size)
{
    const int*   idx     = (const int*)  d_in[0];
    const int*   targets = (const int*)  d_in[1];
    const float* wte     = (const float*)d_in[2];
    const float* W_in    = (const float*)d_in[3];
    const float* W_ih    = (const float*)d_in[4];
    const float* b_ih    = (const float*)d_in[5];
    const float* W_hh    = (const float*)d_in[6];
    const float* b_hh    = (const float*)d_in[7];
    const float* Wh1     = (const float*)d_in[8];
    const float* Wh2     = (const float*)d_in[9];
    float* out = (float*)d_out;

    cudaFuncSetAttribute(scan_kernel, cudaFuncAttributeMaxDynamicSharedMemorySize, SCAN_SMEM);

    float *pC, *pxin, *pstates, *plg1, *plg2;
    cudaGetSymbolAddress((void**)&pC,      g_C);
    cudaGetSymbolAddress((void**)&pxin,    g_xin);
    cudaGetSymbolAddress((void**)&pstates, g_states);
    cudaGetSymbolAddress((void**)&plg1,    g_lg1);
    cudaGetSymbolAddress((void**)&plg2,    g_lg2);

    init_kernel<<<1, 256>>>();

    // C = W_ih @ W_in : [2048, 256]
    gemm_nn_kernel<<<dim3(EMBED/64, RESV/64), 256>>>(W_ih, W_in, pC, RESV, EMBED, RESV);

    // xin[p, s] = wte[idx[p]] . C[s] + b_ih[s] : [2048, 2048]
    gemm_nt_kernel<<<dim3(RESV/64, NPOS/64), 256>>>(
        wte, pC, b_ih, idx, pxin, NPOS, RESV, EMBED, 1, 1);

    // recurrent scan -> g_states (+ g_h double buffer)
    scan_kernel<<<SCAN_CTAS, 256, SCAN_SMEM>>>(W_hh, b_hh);

    // fused dual head GEMM (z = 0 -> Wh1/lg1, z = 1 -> Wh2/lg2)
    gemm_heads_kernel<<<dim3((SQV+63)/64, NPOS/64, 2), 256>>>(
        pstates, Wh1, Wh2, plg1, plg2);

    // log-softmax in place (warp per row)
    logsoftmax_kernel<<<(NPOS*32 + 127)/128, 128>>>(plg1);
    logsoftmax_kernel<<<(NPOS*32 + 127)/128, 128>>>(plg2);

    // loss pieces
    nll_kernel<<<(NPOS + 255)/256, 256>>>(targets);
    finalize_kernel<<<1, 1024>>>(out);

    // full-vocab logits expansion
    expand_kernel<<<NPOS, 256>>>(plg1, plg2, out);
}